// round 9
// baseline (speedup 1.0000x reference)
#include <cuda_runtime.h>
#include <cstdint>

// ---------------------------------------------------------------------------
// Problem dims
// ---------------------------------------------------------------------------
#define TSTEPS 512
#define NB     64
#define HID    256
#define MROWS  (TSTEPS * NB)      // 32768
#define NCOLS  1024               // 4*HID
#define KDIM   256
#define NCLASS 5

#define CLUSTER_NCTAS 8
#define NJ   32                    // j-cols per CTA (rank)
#define NBL  8                     // batches per cluster/CTA
#define REC_SMEM (131072 + 16384)  // 128KB U slice + 16KB dbl-buffered h

// ---------------------------------------------------------------------------
// Scratch (static __device__ arrays: allocation-free, allowed)
// ---------------------------------------------------------------------------
__device__ __align__(128) float g_Z [2u * MROWS * NCOLS];   // gate preactivations
__device__ __align__(128) float g_H1[2u * MROWS * HID];     // layer-1 hidden outputs
__device__ __align__(128) float g_H2[2u * MROWS * HID];     // layer-2 hidden outputs
__device__ int g_tok32 = 1;                                 // token dtype flag

// ---------------------------------------------------------------------------
// Math helpers
// ---------------------------------------------------------------------------
__device__ __forceinline__ float fsig(float x) {
    x = fminf(fmaxf(x, -30.f), 30.f);
    return __fdividef(1.f, 1.f + __expf(-x));
}
__device__ __forceinline__ float ftanh_(float x) {
    x = fminf(fmaxf(x, -15.f), 15.f);
    float e = __expf(-2.f * x);
    return __fdividef(1.f - e, 1.f + e);
}
__device__ __forceinline__ int load_token(const void* tokens, int is32, int idx) {
    if (is32) return ((const int*)tokens)[idx];
    return (int)((const long long*)tokens)[idx];
}

// ---------------------------------------------------------------------------
// Prep: token dtype probe (int64 LE -> all odd int32 words zero).
// ---------------------------------------------------------------------------
__global__ void prep_kernel(const void* __restrict__ tokens) {
    __shared__ int flag;
    const int tid = threadIdx.x;
    if (tid == 0) flag = 0;
    __syncthreads();
    const int* p = (const int*)tokens;
    int local = 0;
    for (int i = 1 + 2 * tid; i < MROWS; i += 2 * 256) local |= p[i];
    if (local) atomicOr(&flag, 1);
    __syncthreads();
    if (tid == 0) g_tok32 = (flag != 0) ? 1 : 0;
}

// ---------------------------------------------------------------------------
// SGEMM: C[dir] = A @ W[dir] + bias[dir]   (unchanged — isolation)
// ---------------------------------------------------------------------------
__global__ void __launch_bounds__(256) gemm_kernel(
    const float* __restrict__ embed,
    const void*  __restrict__ tokens,
    const float* __restrict__ W_fw,
    const float* __restrict__ W_bw,
    const float* __restrict__ b_fw,
    const float* __restrict__ b_bw,
    int mode)
{
    __shared__ __align__(16) float As[16][132];
    __shared__ __align__(16) float Bs[16][128];
    __shared__ int sTok[128];

    const int tid = threadIdx.x;
    const int dir = blockIdx.z;
    const int m0  = blockIdx.y * 128;
    const int n0  = blockIdx.x * 128;

    const float* Wm   = dir ? W_bw : W_fw;
    const float* bias = dir ? b_bw : b_fw;

    if (mode == 0 && tid < 128) {
        int r = m0 + tid;
        int s = r >> 6, b = r & 63;
        int tt = (dir == 0) ? s : (TSTEPS - 1 - s);
        sTok[tid] = load_token(tokens, g_tok32, b * TSTEPS + tt);
    }
    __syncthreads();

    const int ty = tid >> 4;
    const int tx = tid & 15;

    float acc[8][8];
#pragma unroll
    for (int i = 0; i < 8; i++)
#pragma unroll
        for (int j = 0; j < 8; j++) acc[i][j] = 0.f;

    for (int kt = 0; kt < KDIM; kt += 16) {
#pragma unroll
        for (int i = 0; i < 2; i++) {
            int idx = tid + i * 256;
            int m   = idx >> 2;
            int kq  = idx & 3;
            const float* arow;
            if (mode == 0) arow = embed + (size_t)sTok[m] * KDIM;
            else           arow = g_H1 + (size_t)dir * MROWS * HID + (size_t)(m0 + m) * HID;
            float4 v = *(const float4*)(arow + kt + kq * 4);
            As[kq * 4 + 0][m] = v.x;
            As[kq * 4 + 1][m] = v.y;
            As[kq * 4 + 2][m] = v.z;
            As[kq * 4 + 3][m] = v.w;
        }
#pragma unroll
        for (int i = 0; i < 2; i++) {
            int idx = tid + i * 256;
            int k   = idx >> 5;
            int nq  = idx & 31;
            *(float4*)&Bs[k][nq * 4] =
                *(const float4*)(Wm + (size_t)(kt + k) * NCOLS + n0 + nq * 4);
        }
        __syncthreads();

#pragma unroll
        for (int kk = 0; kk < 16; kk++) {
            float a[8], bb[8];
            *(float4*)&a[0]  = *(const float4*)&As[kk][ty * 8];
            *(float4*)&a[4]  = *(const float4*)&As[kk][ty * 8 + 4];
            *(float4*)&bb[0] = *(const float4*)&Bs[kk][tx * 8];
            *(float4*)&bb[4] = *(const float4*)&Bs[kk][tx * 8 + 4];
#pragma unroll
            for (int i = 0; i < 8; i++)
#pragma unroll
                for (int j = 0; j < 8; j++)
                    acc[i][j] = fmaf(a[i], bb[j], acc[i][j]);
        }
        __syncthreads();
    }

    float bv[8];
#pragma unroll
    for (int j = 0; j < 8; j++) bv[j] = bias[n0 + tx * 8 + j];

    float* Cd = g_Z + (size_t)dir * MROWS * NCOLS;
#pragma unroll
    for (int i = 0; i < 8; i++) {
        size_t r = (size_t)(m0 + ty * 8 + i);
        float* cp = Cd + r * NCOLS + n0 + tx * 8;
        float4 o0, o1;
        o0.x = acc[i][0] + bv[0]; o0.y = acc[i][1] + bv[1];
        o0.z = acc[i][2] + bv[2]; o0.w = acc[i][3] + bv[3];
        o1.x = acc[i][4] + bv[4]; o1.y = acc[i][5] + bv[5];
        o1.z = acc[i][6] + bv[6]; o1.w = acc[i][7] + bv[7];
        *(float4*)cp       = o0;
        *((float4*)cp + 1) = o1;
    }
}

// ---------------------------------------------------------------------------
// Recurrent phase — CGA-cluster version.
// Grid = 128 CTAs = 16 independent clusters of 8.
// Cluster = (dir 0..1, bb 0..7): owns an 8-batch block, full 256 hidden.
// Rank r in cluster owns j in [32r, 32r+32). Thread = (jl 0..31, bl 0..7),
// tid = jl*8 + bl (warp = 4 j x 8 b so the U LDS.128 is 4-way distinct +
// 8-way broadcast; h LDS is 8 distinct 4B).
//
// Exchange: after computing h, each thread pushes h into ALL 8 cluster
// CTAs' s_h[parity][j][bl] via st.shared::cluster (mapa-translated), then
// barrier.cluster.arrive (release). Next tick's barrier.cluster.wait
// (acquire) makes h visible; matvec reads it from LOCAL smem. No flags,
// no L2 round trips, no fences, no fill phase. Clusters are mutually
// independent -> no cross-cluster residency requirement.
// ---------------------------------------------------------------------------
__global__ void __launch_bounds__(256, 1) __cluster_dims__(CLUSTER_NCTAS, 1, 1)
rec_kernel(
    const float* __restrict__ U_fw,
    const float* __restrict__ U_bw,
    int layer)
{
    extern __shared__ float smem[];
    float* sU  = smem;                  // [k=256][j=32][g=4] floats (128KB)
    float* s_h = smem + 32768;          // [2][k=256][b=8]   floats (16KB)

    const int cid = blockIdx.x;
    const int dir = cid >> 6;                  // same for all cluster members
    const int bb  = (cid >> 3) & 7;            // same for all cluster members
    uint32_t rank;
    asm("mov.u32 %0, %%cluster_ctarank;" : "=r"(rank));

    const int tid = threadIdx.x;
    const int jl  = tid >> 3;                  // 0..31
    const int bl  = tid & 7;                   // 0..7
    const int j0  = (int)rank * NJ;
    const int jg  = j0 + jl;                   // global hidden idx 0..255
    const int b   = bb * NBL + bl;             // global batch 0..63

    const float* U = dir ? U_bw : U_fw;

    // ---- cache this rank's U slice: sU[(k*32+jj)*4+g] = U[k][g*256 + j0+jj]
    for (int i = tid; i < NJ * 4 * KDIM; i += 256) {
        int jj = i & 31, g = (i >> 5) & 3, k = i >> 7;
        sU[(k * 32 + jj) * 4 + g] = U[(size_t)k * NCOLS + g * HID + j0 + jj];
    }
    __syncthreads();

    // ---- peer smem addresses for the h push (all 8 ranks incl. self)
    uint32_t sh_base = (uint32_t)__cvta_generic_to_shared(s_h);
    uint32_t peer[CLUSTER_NCTAS];
#pragma unroll
    for (int r = 0; r < CLUSTER_NCTAS; r++) {
        asm("mapa.shared::cluster.u32 %0, %1, %2;"
            : "=r"(peer[r]) : "r"(sh_base), "r"(r));
    }

    const unsigned sU_addr = (unsigned)__cvta_generic_to_shared(sU) + (unsigned)(jl * 16);
    const float* Zd = g_Z + (size_t)dir * MROWS * NCOLS;
    float* Hd       = (layer ? g_H2 : g_H1) + (size_t)dir * MROWS * HID;

    // first-step Z (streamed)
    size_t zrow0 = (size_t)b * NCOLS;
    float4 z;
    z.x = __ldcs(&Zd[zrow0 + 0 * HID + jg]);
    z.y = __ldcs(&Zd[zrow0 + 1 * HID + jg]);
    z.z = __ldcs(&Zd[zrow0 + 2 * HID + jg]);
    z.w = __ldcs(&Zd[zrow0 + 3 * HID + jg]);

    float c = 0.f;

    for (int s = 0; s < TSTEPS; s++) {
        unsigned long long acc01, acc23;
        asm("mov.b64 %0,{%1,%2};" : "=l"(acc01)
            : "r"(__float_as_uint(z.x)), "r"(__float_as_uint(z.y)));
        asm("mov.b64 %0,{%1,%2};" : "=l"(acc23)
            : "r"(__float_as_uint(z.z)), "r"(__float_as_uint(z.w)));

        if (s > 0) {
            // h[s-1] landed in local s_h; acquire it
            asm volatile("barrier.cluster.wait.aligned;" ::: "memory");

            const float* shp = s_h + ((s - 1) & 1) * (KDIM * NBL) + bl;
#pragma unroll 16
            for (int k = 0; k < KDIM; k++) {
                float hv = shp[k * NBL];
                unsigned long long hh, u01, u23;
                asm("mov.b64 %0,{%1,%1};" : "=l"(hh) : "r"(__float_as_uint(hv)));
                asm("ld.shared.v2.b64 {%0,%1},[%2];" : "=l"(u01), "=l"(u23)
                    : "r"(sU_addr + (unsigned)(k * (NJ * 16))));
                asm("fma.rn.f32x2 %0,%1,%2,%0;" : "+l"(acc01) : "l"(u01), "l"(hh));
                asm("fma.rn.f32x2 %0,%1,%2,%0;" : "+l"(acc23) : "l"(u23), "l"(hh));
            }
        }

        unsigned r0, r1, r2, r3;
        asm("mov.b64 {%0,%1},%2;" : "=r"(r0), "=r"(r1) : "l"(acc01));
        asm("mov.b64 {%0,%1},%2;" : "=r"(r2), "=r"(r3) : "l"(acc23));

        float ig = fsig(__uint_as_float(r0));
        float fg = fsig(__uint_as_float(r1));
        float gg = ftanh_(__uint_as_float(r2));
        float og = fsig(__uint_as_float(r3));
        c = fg * c + ig * gg;
        float h = og * ftanh_(c);

        if (s < TSTEPS - 1) {
            // push h to every cluster CTA's s_h[s&1][jg][bl]
            uint32_t off = ((uint32_t)((s & 1) * (KDIM * NBL) + jg * NBL + bl)) * 4u;
#pragma unroll
            for (int r = 0; r < CLUSTER_NCTAS; r++) {
                asm volatile("st.shared::cluster.f32 [%0], %1;"
                             :: "r"(peer[r] + off), "f"(h) : "memory");
            }
            asm volatile("barrier.cluster.arrive.aligned;" ::: "memory");
        }

        // off-critical-path: sequence output + Z[s+1] prefetch
        __stcs(&Hd[((size_t)s * NB + b) * HID + jg], h);
        if (s < TSTEPS - 1) {
            size_t zrow = ((size_t)(s + 1) * NB + b) * NCOLS;
            z.x = __ldcs(&Zd[zrow + 0 * HID + jg]);
            z.y = __ldcs(&Zd[zrow + 1 * HID + jg]);
            z.z = __ldcs(&Zd[zrow + 2 * HID + jg]);
            z.w = __ldcs(&Zd[zrow + 3 * HID + jg]);
        }
    }
}

// ---------------------------------------------------------------------------
// Output head: concat(fw, bw) @ dense_W + b, softmax over 5 classes.
// ---------------------------------------------------------------------------
__global__ void __launch_bounds__(256) dense_kernel(
    const float* __restrict__ Wd,
    const float* __restrict__ bd,
    float* __restrict__ out)
{
    __shared__ float sW[2 * HID * NCLASS];
    __shared__ float sb[NCLASS];
    const int tid = threadIdx.x;
    for (int i = tid; i < 2 * HID * NCLASS; i += 256) sW[i] = Wd[i];
    if (tid < NCLASS) sb[tid] = bd[tid];
    __syncthreads();

    int gid = blockIdx.x * 256 + tid;      // b*512 + t
    int b = gid >> 9, t = gid & 511;

    const float* hf = g_H2 + ((size_t)t * NB + b) * HID;
    const float* hb = g_H2 + (size_t)MROWS * HID + ((size_t)(TSTEPS - 1 - t) * NB + b) * HID;

    float acc[NCLASS];
#pragma unroll
    for (int cc = 0; cc < NCLASS; cc++) acc[cc] = sb[cc];

    for (int jj = 0; jj < HID; jj++) {
        float v = hf[jj];
#pragma unroll
        for (int cc = 0; cc < NCLASS; cc++)
            acc[cc] = fmaf(v, sW[jj * NCLASS + cc], acc[cc]);
    }
    for (int jj = 0; jj < HID; jj++) {
        float v = hb[jj];
#pragma unroll
        for (int cc = 0; cc < NCLASS; cc++)
            acc[cc] = fmaf(v, sW[(HID + jj) * NCLASS + cc], acc[cc]);
    }

    float m = acc[0];
#pragma unroll
    for (int cc = 1; cc < NCLASS; cc++) m = fmaxf(m, acc[cc]);
    float e[NCLASS], sum = 0.f;
#pragma unroll
    for (int cc = 0; cc < NCLASS; cc++) { e[cc] = __expf(acc[cc] - m); sum += e[cc]; }
    float inv = __fdividef(1.f, sum);
#pragma unroll
    for (int cc = 0; cc < NCLASS; cc++) out[(size_t)gid * NCLASS + cc] = e[cc] * inv;
}

// ---------------------------------------------------------------------------
// Launcher (graph-capturable: kernel launches only, default stream)
// ---------------------------------------------------------------------------
extern "C" void kernel_launch(void* const* d_in, const int* in_sizes, int n_in,
                              void* d_out, int out_size)
{
    const void*  tokens  = d_in[0];
    const float* embed   = (const float*)d_in[1];
    const float* fw_W1   = (const float*)d_in[2];
    const float* fw_U1   = (const float*)d_in[3];
    const float* fw_b1   = (const float*)d_in[4];
    const float* fw_W2   = (const float*)d_in[5];
    const float* fw_U2   = (const float*)d_in[6];
    const float* fw_b2   = (const float*)d_in[7];
    const float* bw_W1   = (const float*)d_in[8];
    const float* bw_U1   = (const float*)d_in[9];
    const float* bw_b1   = (const float*)d_in[10];
    const float* bw_W2   = (const float*)d_in[11];
    const float* bw_U2   = (const float*)d_in[12];
    const float* bw_b2   = (const float*)d_in[13];
    const float* dense_W = (const float*)d_in[14];
    const float* dense_b = (const float*)d_in[15];
    float* out = (float*)d_out;

    cudaFuncSetAttribute(rec_kernel, cudaFuncAttributeMaxDynamicSharedMemorySize, REC_SMEM);

    prep_kernel<<<1, 256>>>(tokens);

    gemm_kernel<<<dim3(8, 256, 2), 256>>>(embed, tokens, fw_W1, bw_W1, fw_b1, bw_b1, 0);
    rec_kernel<<<128, 256, REC_SMEM>>>(fw_U1, bw_U1, 0);
    gemm_kernel<<<dim3(8, 256, 2), 256>>>(embed, tokens, fw_W2, bw_W2, fw_b2, bw_b2, 1);
    rec_kernel<<<128, 256, REC_SMEM>>>(fw_U2, bw_U2, 1);
    dense_kernel<<<MROWS / 256, 256>>>(dense_W, dense_b, out);
}